// round 1
// baseline (speedup 1.0000x reference)
#include <cuda_runtime.h>
#include <cstdint>

#define NB 16
#define NS 1024
#define NE 512
#define ND 512

constexpr long BSROWS = (long)NB * NS;        // 16384
constexpr long XSZ = BSROWS * NE;             // 8388608 elems (32MB)
constexpr long WSZ = (long)NB * NS * NS;      // 16777216 elems (64MB)

// Scratch (device globals; no allocation in kernel_launch)
__device__ float g_X[XSZ];
__device__ float g_Q[XSZ];
__device__ float g_K[XSZ];
__device__ float g_V[XSZ];
__device__ float g_WM[XSZ];
__device__ float g_H[XSZ];
__device__ float g_rowsum[BSROWS];

// ---------------------------------------------------------------------------
// helpers
// ---------------------------------------------------------------------------
__device__ __forceinline__ float tf32r(float x) {
    uint32_t u;
    asm("cvt.rna.tf32.f32 %0, %1;" : "=r"(u) : "f"(x));
    return __uint_as_float(u);
}

__device__ __forceinline__ void mma_tf32(float* c, const uint32_t* a, const uint32_t* b) {
    asm volatile(
        "mma.sync.aligned.m16n8k8.row.col.f32.tf32.tf32.f32 "
        "{%0,%1,%2,%3},{%4,%5,%6,%7},{%8,%9},{%0,%1,%2,%3};"
        : "+f"(c[0]), "+f"(c[1]), "+f"(c[2]), "+f"(c[3])
        : "r"(a[0]), "r"(a[1]), "r"(a[2]), "r"(a[3]), "r"(b[0]), "r"(b[1]));
}

// ---------------------------------------------------------------------------
// 1) embedding gather: X[row,:] = embed_table[inputs[row],:]
// ---------------------------------------------------------------------------
__global__ void gather_kernel(const int* __restrict__ inputs,
                              const float* __restrict__ table,
                              float* __restrict__ X) {
    long row = blockIdx.x;
    long src = (long)inputs[row] * NE;
    float4 v = *(const float4*)(table + src + threadIdx.x * 4);
    *(float4*)(X + row * NE + threadIdx.x * 4) = v;
}

// ---------------------------------------------------------------------------
// 2) generic tf32 GEMM: C = A[M,K] @ B[K,N] (+bias) (+tanh), batched via z.
//    BM=128, BN=128, BK=16, 256 threads = 8 warps (4m x 2n), warp tile 32x64.
//    EPI: 0 = none, 1 = +bias, 2 = tanh(+bias)
// ---------------------------------------------------------------------------
template <int EPI>
__global__ __launch_bounds__(256) void gemm_tf32(
    const float* __restrict__ A, const float* __restrict__ Bm,
    const float* __restrict__ bias, float* __restrict__ C,
    int M, int N, int K, long sA, long sB, long sC) {
    constexpr int BM = 128, BN = 128, BK = 16;
    __shared__ float As[BK][BM + 4];
    __shared__ float Bs[BK][BN + 4];

    const int z = blockIdx.z;
    A += (long)z * sA;
    Bm += (long)z * sB;
    C += (long)z * sC;

    const int bm = blockIdx.y * BM, bn = blockIdx.x * BN;
    const int tid = threadIdx.x, warp = tid >> 5, lane = tid & 31;
    const int wm = (warp >> 1) * 32, wn = (warp & 1) * 64;
    const int g = lane >> 2, qd = lane & 3;

    float acc[2][8][4];
#pragma unroll
    for (int i = 0; i < 2; i++)
#pragma unroll
        for (int j = 0; j < 8; j++)
#pragma unroll
            for (int t = 0; t < 4; t++) acc[i][j][t] = 0.f;

    for (int k0 = 0; k0 < K; k0 += BK) {
        __syncthreads();
#pragma unroll
        for (int j = 0; j < 2; j++) {
            int fid = tid + j * 256;
            int m = fid >> 2, k4 = (fid & 3) * 4;
            float4 v = *(const float4*)(A + (long)(bm + m) * K + k0 + k4);
            As[k4 + 0][m] = tf32r(v.x);
            As[k4 + 1][m] = tf32r(v.y);
            As[k4 + 2][m] = tf32r(v.z);
            As[k4 + 3][m] = tf32r(v.w);
        }
#pragma unroll
        for (int j = 0; j < 2; j++) {
            int fid = tid + j * 256;
            int kk = fid >> 5, n4 = (fid & 31) * 4;
            float4 v = *(const float4*)(Bm + (long)(k0 + kk) * N + bn + n4);
            Bs[kk][n4 + 0] = tf32r(v.x);
            Bs[kk][n4 + 1] = tf32r(v.y);
            Bs[kk][n4 + 2] = tf32r(v.z);
            Bs[kk][n4 + 3] = tf32r(v.w);
        }
        __syncthreads();
#pragma unroll
        for (int ks = 0; ks < BK; ks += 8) {
            uint32_t af[2][4];
#pragma unroll
            for (int mt = 0; mt < 2; mt++) {
                af[mt][0] = __float_as_uint(As[ks + qd][wm + mt * 16 + g]);
                af[mt][1] = __float_as_uint(As[ks + qd][wm + mt * 16 + g + 8]);
                af[mt][2] = __float_as_uint(As[ks + qd + 4][wm + mt * 16 + g]);
                af[mt][3] = __float_as_uint(As[ks + qd + 4][wm + mt * 16 + g + 8]);
            }
            uint32_t bf[8][2];
#pragma unroll
            for (int nt = 0; nt < 8; nt++) {
                bf[nt][0] = __float_as_uint(Bs[ks + qd][wn + nt * 8 + g]);
                bf[nt][1] = __float_as_uint(Bs[ks + qd + 4][wn + nt * 8 + g]);
            }
#pragma unroll
            for (int mt = 0; mt < 2; mt++)
#pragma unroll
                for (int nt = 0; nt < 8; nt++) mma_tf32(acc[mt][nt], af[mt], bf[nt]);
        }
    }

#pragma unroll
    for (int mt = 0; mt < 2; mt++) {
        int r0 = bm + wm + mt * 16 + g;
#pragma unroll
        for (int nt = 0; nt < 8; nt++) {
            int c0 = bn + wn + nt * 8 + 2 * qd;
            float v0 = acc[mt][nt][0], v1 = acc[mt][nt][1];
            float v2 = acc[mt][nt][2], v3 = acc[mt][nt][3];
            if (EPI >= 1) {
                float b0 = bias[c0], b1 = bias[c0 + 1];
                v0 += b0; v1 += b1; v2 += b0; v3 += b1;
            }
            if (EPI == 2) {
                v0 = tanhf(v0); v1 = tanhf(v1);
                v2 = tanhf(v2); v3 = tanhf(v3);
            }
            *(float2*)(C + (long)r0 * N + c0) = make_float2(v0, v1);
            *(float2*)(C + (long)(r0 + 8) * N + c0) = make_float2(v2, v3);
        }
    }
}

// ---------------------------------------------------------------------------
// 3) scores kernel: per (b, 128-q tile) block.
//    Computes s = q.k (tf32 mma), then e = (dep==0) ? 0 : exp(s*dep_table[dep]),
//    writes unnormalized e into the weights output region, accumulates row sums.
//    8 warps, warp w owns q rows [w*16, w*16+16), all 1024 keys.
// ---------------------------------------------------------------------------
__global__ __launch_bounds__(256) void scores_kernel(
    const float* __restrict__ Q, const float* __restrict__ Kmat,
    const int* __restrict__ dep, const float* __restrict__ dep_table,
    float* __restrict__ Wout, float* __restrict__ rowsum) {
    __shared__ float Qs[16][128 + 4];
    __shared__ float Ks[16][128 + 4];
    __shared__ float dtab[64];

    const int b = blockIdx.y;
    const int q0 = blockIdx.x * 128;
    const int tid = threadIdx.x, warp = tid >> 5, lane = tid & 31;
    const int g = lane >> 2, qd = lane & 3;
    if (tid < 64) dtab[tid] = dep_table[tid];

    const float* Qb = Q + ((long)b * NS + q0) * ND;
    const float* Kb = Kmat + (long)b * NS * ND;
    const long qrow = (long)b * NS + q0 + warp * 16;

    float rs0 = 0.f, rs1 = 0.f;

    for (int kt = 0; kt < 8; kt++) {
        float acc[16][4];
#pragma unroll
        for (int nt = 0; nt < 16; nt++)
#pragma unroll
            for (int t = 0; t < 4; t++) acc[nt][t] = 0.f;

        for (int d0 = 0; d0 < ND; d0 += 16) {
            __syncthreads();
#pragma unroll
            for (int j = 0; j < 2; j++) {
                int fid = tid + j * 256;
                int m = fid >> 2, k4 = (fid & 3) * 4;
                float4 v = *(const float4*)(Qb + (long)m * ND + d0 + k4);
                Qs[k4 + 0][m] = tf32r(v.x);
                Qs[k4 + 1][m] = tf32r(v.y);
                Qs[k4 + 2][m] = tf32r(v.z);
                Qs[k4 + 3][m] = tf32r(v.w);
                float4 w = *(const float4*)(Kb + (long)(kt * 128 + m) * ND + d0 + k4);
                Ks[k4 + 0][m] = tf32r(w.x);
                Ks[k4 + 1][m] = tf32r(w.y);
                Ks[k4 + 2][m] = tf32r(w.z);
                Ks[k4 + 3][m] = tf32r(w.w);
            }
            __syncthreads();
#pragma unroll
            for (int ks = 0; ks < 16; ks += 8) {
                uint32_t af[4];
                af[0] = __float_as_uint(Qs[ks + qd][warp * 16 + g]);
                af[1] = __float_as_uint(Qs[ks + qd][warp * 16 + g + 8]);
                af[2] = __float_as_uint(Qs[ks + qd + 4][warp * 16 + g]);
                af[3] = __float_as_uint(Qs[ks + qd + 4][warp * 16 + g + 8]);
#pragma unroll
                for (int nt = 0; nt < 16; nt++) {
                    uint32_t bf[2];
                    bf[0] = __float_as_uint(Ks[ks + qd][nt * 8 + g]);
                    bf[1] = __float_as_uint(Ks[ks + qd + 4][nt * 8 + g]);
                    mma_tf32(acc[nt], af, bf);
                }
            }
        }
        // epilogue: dep gather, mask, exp, write unnormalized weights, row sums
#pragma unroll
        for (int nt = 0; nt < 16; nt++) {
            int kc = kt * 128 + nt * 8 + 2 * qd;
            long off0 = (qrow + g) * NS + kc;
            int2 dA = *(const int2*)(dep + off0);
            float e0 = dA.x ? __expf(acc[nt][0] * dtab[dA.x]) : 0.f;
            float e1 = dA.y ? __expf(acc[nt][1] * dtab[dA.y]) : 0.f;
            *(float2*)(Wout + off0) = make_float2(e0, e1);
            rs0 += e0 + e1;
            long off1 = (qrow + g + 8) * NS + kc;
            int2 dB = *(const int2*)(dep + off1);
            float e2 = dB.x ? __expf(acc[nt][2] * dtab[dB.x]) : 0.f;
            float e3 = dB.y ? __expf(acc[nt][3] * dtab[dB.y]) : 0.f;
            *(float2*)(Wout + off1) = make_float2(e2, e3);
            rs1 += e2 + e3;
        }
    }

    rs0 += __shfl_xor_sync(0xffffffff, rs0, 1);
    rs0 += __shfl_xor_sync(0xffffffff, rs0, 2);
    rs1 += __shfl_xor_sync(0xffffffff, rs1, 1);
    rs1 += __shfl_xor_sync(0xffffffff, rs1, 2);
    if (qd == 0) {
        rowsum[qrow + g] = rs0;
        rowsum[qrow + g + 8] = rs1;
    }
}

// ---------------------------------------------------------------------------
// 4) normalize weights in place: W[row, :] *= 1/rowsum[row]
// ---------------------------------------------------------------------------
__global__ void normalize_kernel(float* __restrict__ W, const float* __restrict__ rowsum) {
    long i = ((long)blockIdx.x * 256 + threadIdx.x) * 4;
    float r = __frcp_rn(rowsum[i >> 10]);
    float4 v = *(float4*)(W + i);
    v.x *= r; v.y *= r; v.z *= r; v.w *= r;
    *(float4*)(W + i) = v;
}

// ---------------------------------------------------------------------------
// launch
// ---------------------------------------------------------------------------
extern "C" void kernel_launch(void* const* d_in, const int* in_sizes, int n_in,
                              void* d_out, int out_size) {
    const int* inputs      = (const int*)d_in[0];
    const int* dependency  = (const int*)d_in[1];
    const float* embed     = (const float*)d_in[2];
    const float* dep_table = (const float*)d_in[3];
    const float* Wq = (const float*)d_in[4];
    const float* bq = (const float*)d_in[5];
    const float* Wk = (const float*)d_in[6];
    const float* bk = (const float*)d_in[7];
    const float* Wv = (const float*)d_in[8];
    const float* bv = (const float*)d_in[9];
    const float* W1 = (const float*)d_in[10];
    const float* b1 = (const float*)d_in[11];
    const float* W2 = (const float*)d_in[12];
    const float* b2 = (const float*)d_in[13];

    float* out = (float*)d_out;
    float* out_wm = out;          // [B,S,D] first (reference return order)
    float* out_w  = out + XSZ;    // [B,S,S]

    float *X, *Qp, *Kp, *Vp, *WM, *H, *RS;
    cudaGetSymbolAddress((void**)&X, g_X);
    cudaGetSymbolAddress((void**)&Qp, g_Q);
    cudaGetSymbolAddress((void**)&Kp, g_K);
    cudaGetSymbolAddress((void**)&Vp, g_V);
    cudaGetSymbolAddress((void**)&WM, g_WM);
    cudaGetSymbolAddress((void**)&H, g_H);
    cudaGetSymbolAddress((void**)&RS, g_rowsum);

    // 1) x = embed[inputs]
    gather_kernel<<<16384, 128>>>(inputs, embed, X);

    // 2) q,k,v projections
    dim3 gproj(ND / 128, 16384 / 128, 1);
    gemm_tf32<1><<<gproj, 256>>>(X, Wq, bq, Qp, 16384, ND, NE, 0, 0, 0);
    gemm_tf32<1><<<gproj, 256>>>(X, Wk, bk, Kp, 16384, ND, NE, 0, 0, 0);
    gemm_tf32<1><<<gproj, 256>>>(X, Wv, bv, Vp, 16384, ND, NE, 0, 0, 0);

    // 3) scores + exp + mask (unnormalized weights into output) + row sums
    scores_kernel<<<dim3(NS / 128, NB), 256>>>(Qp, Kp, dependency, dep_table, out_w, RS);

    // 4) normalize weights in place
    normalize_kernel<<<(int)(WSZ / 4 / 256), 256>>>(out_w, RS);

    // 5) wm_raw = weights @ V   (batched over b)
    gemm_tf32<0><<<dim3(ND / 128, NS / 128, NB), 256>>>(
        out_w, Vp, nullptr, WM, NS, ND, NS,
        (long)NS * NS, (long)NS * ND, (long)NS * ND);

    // 6) h = tanh(wm @ W1 + b1)
    gemm_tf32<2><<<gproj, 256>>>(WM, W1, b1, H, 16384, ND, ND, 0, 0, 0);

    // 7) out_wm = h @ W2 + b2
    gemm_tf32<1><<<gproj, 256>>>(H, W2, b2, out_wm, 16384, ND, ND, 0, 0, 0);
}

// round 2
// speedup vs baseline: 1.8008x; 1.8008x over previous
#include <cuda_runtime.h>
#include <cstdint>

#define NB 16
#define NS 1024
#define NE 512
#define ND 512

constexpr long BSROWS = (long)NB * NS;        // 16384
constexpr long XSZ = BSROWS * NE;             // 8388608
constexpr long WSZ = (long)NB * NS * NS;      // 16777216
constexpr int  WELEMS = 512 * 512;            // one weight matrix

// Scratch (device globals)
__device__ float g_X[XSZ];
__device__ float g_Q[XSZ];
__device__ float g_K[XSZ];
__device__ float g_V[XSZ];
__device__ float g_WM[XSZ];
__device__ float g_H[XSZ];
__device__ float g_Wr[5L * WELEMS];
__device__ float g_rowsum2[2 * BSROWS];

// ---------------------------------------------------------------------------
// helpers
// ---------------------------------------------------------------------------
__device__ __forceinline__ float tf32r(float x) {
    uint32_t u;
    asm("cvt.rna.tf32.f32 %0, %1;" : "=r"(u) : "f"(x));
    return __uint_as_float(u);
}

__device__ __forceinline__ void mma_tf32(float* c, const uint32_t* a, const uint32_t* b) {
    asm volatile(
        "mma.sync.aligned.m16n8k8.row.col.f32.tf32.tf32.f32 "
        "{%0,%1,%2,%3},{%4,%5,%6,%7},{%8,%9},{%0,%1,%2,%3};"
        : "+f"(c[0]), "+f"(c[1]), "+f"(c[2]), "+f"(c[3])
        : "r"(a[0]), "r"(a[1]), "r"(a[2]), "r"(a[3]), "r"(b[0]), "r"(b[1]));
}

__device__ __forceinline__ uint32_t s2u(const void* p) {
    return (uint32_t)__cvta_generic_to_shared(p);
}
__device__ __forceinline__ void cpa16(uint32_t dst, const float* src) {
    asm volatile("cp.async.cg.shared.global [%0], [%1], 16;"
                 :: "r"(dst), "l"(__cvta_generic_to_global((const void*)src)));
}
__device__ __forceinline__ void cp_commit() {
    asm volatile("cp.async.commit_group;");
}

// ---------------------------------------------------------------------------
// 0) pre-round the 5 harness weight matrices to tf32 (one-time per launch)
// ---------------------------------------------------------------------------
__global__ void preround5(const float* __restrict__ w0, const float* __restrict__ w1,
                          const float* __restrict__ w2, const float* __restrict__ w3,
                          const float* __restrict__ w4, float* __restrict__ out) {
    int z = blockIdx.y;
    const float* src = (z == 0) ? w0 : (z == 1) ? w1 : (z == 2) ? w2 : (z == 3) ? w3 : w4;
    long i = ((long)blockIdx.x * 256 + threadIdx.x) * 4;
    float4 v = *(const float4*)(src + i);
    v.x = tf32r(v.x); v.y = tf32r(v.y); v.z = tf32r(v.z); v.w = tf32r(v.w);
    *(float4*)(out + (long)z * WELEMS + i) = v;
}

// ---------------------------------------------------------------------------
// 1) embedding gather (rounds X to tf32; X only feeds mma)
// ---------------------------------------------------------------------------
__global__ void gather_kernel(const int* __restrict__ inputs,
                              const float* __restrict__ table,
                              float* __restrict__ X) {
    long row = blockIdx.x;
    long src = (long)inputs[row] * NE;
    float4 v = *(const float4*)(table + src + threadIdx.x * 4);
    v.x = tf32r(v.x); v.y = tf32r(v.y); v.z = tf32r(v.z); v.w = tf32r(v.w);
    *(float4*)(X + row * NE + threadIdx.x * 4) = v;
}

// ---------------------------------------------------------------------------
// 2) pipelined tf32 GEMM: C = A[M,K] @ B[K,N] (+bias)(+tanh)(+tf32-round)
//    BM=BN=128, BK=32, 128 threads = 4 warps, warp tile 64x64.
//    2-stage cp.async double buffer. A layout [m][k] (stride 36),
//    B layout [k][n] (stride 136) — both conflict-free for frag loads.
// ---------------------------------------------------------------------------
constexpr int ASTR = 36;
constexpr int BSTR = 136;
constexpr int A_STAGE = 128 * ASTR;   // floats
constexpr int B_STAGE = 32 * BSTR;
constexpr int GEMM_SMEM = (2 * (A_STAGE + B_STAGE)) * 4;  // 71680 B

template <int EPI, bool CVTA, bool RND>
__global__ __launch_bounds__(128) void gemm_pipe(
    const float* __restrict__ A, const float* __restrict__ B,
    const float* __restrict__ bias, float* __restrict__ C,
    int N, int K, int lda, int ldb, int ldc, long sA, long sB, long sC) {
    extern __shared__ float sm[];
    float* As = sm;                    // [2][128][ASTR]
    float* Bs = sm + 2 * A_STAGE;      // [2][32][BSTR]

    const int z = blockIdx.z;
    A += (long)z * sA; B += (long)z * sB; C += (long)z * sC;
    const int bm = blockIdx.y * 128, bn = blockIdx.x * 128;
    const int tid = threadIdx.x, warp = tid >> 5, lane = tid & 31;
    const int wm = (warp >> 1) * 64, wn = (warp & 1) * 64;
    const int g = lane >> 2, qd = lane & 3;

    float acc[4][8][4];
#pragma unroll
    for (int i = 0; i < 4; i++)
#pragma unroll
        for (int j = 0; j < 8; j++)
#pragma unroll
            for (int t = 0; t < 4; t++) acc[i][j][t] = 0.f;

    const int nit = K / 32;

    auto load_stage = [&](int s, int k0) {
        float* as = As + s * A_STAGE;
        float* bs = Bs + s * B_STAGE;
#pragma unroll
        for (int j = 0; j < 8; j++) {
            int idx = tid + j * 128;
            int row = idx >> 3, seg = idx & 7;
            cpa16(s2u(as + row * ASTR + seg * 4),
                  A + (long)(bm + row) * lda + k0 + seg * 4);
        }
#pragma unroll
        for (int j = 0; j < 8; j++) {
            int idx = tid + j * 128;
            int kk = idx >> 5, seg = idx & 31;
            cpa16(s2u(bs + kk * BSTR + seg * 4),
                  B + (long)(k0 + kk) * ldb + bn + seg * 4);
        }
        cp_commit();
    };

    load_stage(0, 0);
    for (int it = 0; it < nit; ++it) {
        if (it + 1 < nit) {
            load_stage((it + 1) & 1, (it + 1) * 32);
            asm volatile("cp.async.wait_group 1;" ::: "memory");
        } else {
            asm volatile("cp.async.wait_group 0;" ::: "memory");
        }
        __syncthreads();
        const float* as = As + (it & 1) * A_STAGE;
        const float* bs = Bs + (it & 1) * B_STAGE;
#pragma unroll
        for (int ks = 0; ks < 32; ks += 8) {
            uint32_t af[4][4], bf[8][2];
#pragma unroll
            for (int mt = 0; mt < 4; mt++) {
                const float* ar = as + (wm + mt * 16 + g) * ASTR + ks + qd;
                float a0 = ar[0], a1 = ar[8 * ASTR], a2 = ar[4], a3 = ar[8 * ASTR + 4];
                if (CVTA) { a0 = tf32r(a0); a1 = tf32r(a1); a2 = tf32r(a2); a3 = tf32r(a3); }
                af[mt][0] = __float_as_uint(a0); af[mt][1] = __float_as_uint(a1);
                af[mt][2] = __float_as_uint(a2); af[mt][3] = __float_as_uint(a3);
            }
#pragma unroll
            for (int nt = 0; nt < 8; nt++) {
                bf[nt][0] = __float_as_uint(bs[(ks + qd) * BSTR + wn + nt * 8 + g]);
                bf[nt][1] = __float_as_uint(bs[(ks + qd + 4) * BSTR + wn + nt * 8 + g]);
            }
#pragma unroll
            for (int mt = 0; mt < 4; mt++)
#pragma unroll
                for (int nt = 0; nt < 8; nt++) mma_tf32(acc[mt][nt], af[mt], bf[nt]);
        }
        __syncthreads();
    }

#pragma unroll
    for (int mt = 0; mt < 4; mt++) {
        int r0 = bm + wm + mt * 16 + g;
#pragma unroll
        for (int nt = 0; nt < 8; nt++) {
            int c0 = bn + wn + nt * 8 + 2 * qd;
            float v0 = acc[mt][nt][0], v1 = acc[mt][nt][1];
            float v2 = acc[mt][nt][2], v3 = acc[mt][nt][3];
            if (EPI >= 1) {
                float b0 = bias[c0], b1 = bias[c0 + 1];
                v0 += b0; v1 += b1; v2 += b0; v3 += b1;
            }
            if (EPI == 2) { v0 = tanhf(v0); v1 = tanhf(v1); v2 = tanhf(v2); v3 = tanhf(v3); }
            if (RND) { v0 = tf32r(v0); v1 = tf32r(v1); v2 = tf32r(v2); v3 = tf32r(v3); }
            *(float2*)(C + (long)r0 * ldc + c0) = make_float2(v0, v1);
            *(float2*)(C + (long)(r0 + 8) * ldc + c0) = make_float2(v2, v3);
        }
    }
}

// ---------------------------------------------------------------------------
// 3) scores: per (q-tile 128, key-half 512, batch) block.
//    S = Q K^T (pipelined tf32 mma), e = dep? exp(s*dtab[dep]) : 0,
//    writes unnormalized e to weights output, partial rowsums to g_rowsum2.
// ---------------------------------------------------------------------------
constexpr int Q_STAGE = 128 * ASTR;   // Q and K both [row][d] stride 36
constexpr int SC_SMEM = (4 * Q_STAGE + 64 + 256) * 4;  // 75008 B

__global__ __launch_bounds__(128) void scores_pipe(
    const float* __restrict__ Q, const float* __restrict__ Km,
    const int* __restrict__ dep, const float* __restrict__ dep_table,
    float* __restrict__ Wout, float* __restrict__ rowsum2) {
    extern __shared__ float sm[];
    float* Qs = sm;                       // [2][128][ASTR]
    float* Ks = sm + 2 * Q_STAGE;         // [2][128][ASTR]
    float* dtab = sm + 4 * Q_STAGE;       // [64]
    float* rs2 = dtab + 64;               // [2][128]

    const int b = blockIdx.z, half = blockIdx.y;
    const int q0 = blockIdx.x * 128;
    const int tid = threadIdx.x, warp = tid >> 5, lane = tid & 31;
    const int wm = (warp >> 1) * 64, wn = (warp & 1) * 64;
    const int g = lane >> 2, qd = lane & 3;
    if (tid < 64) dtab[tid] = dep_table[tid];

    const float* Qb = Q + ((long)b * NS + q0) * ND;
    const float* Kb = Km + (long)b * NS * ND;

    float rs[4][2];
#pragma unroll
    for (int mt = 0; mt < 4; mt++) { rs[mt][0] = 0.f; rs[mt][1] = 0.f; }

    for (int kt = half * 4; kt < half * 4 + 4; kt++) {
        const float* Kt = Kb + (long)kt * 128 * ND;
        float acc[4][8][4];
#pragma unroll
        for (int i = 0; i < 4; i++)
#pragma unroll
            for (int j = 0; j < 8; j++)
#pragma unroll
                for (int t = 0; t < 4; t++) acc[i][j][t] = 0.f;

        auto load_stage = [&](int s, int d0) {
            float* qs = Qs + s * Q_STAGE;
            float* ks = Ks + s * Q_STAGE;
#pragma unroll
            for (int j = 0; j < 8; j++) {
                int idx = tid + j * 128;
                int row = idx >> 3, seg = idx & 7;
                cpa16(s2u(qs + row * ASTR + seg * 4), Qb + (long)row * ND + d0 + seg * 4);
                cpa16(s2u(ks + row * ASTR + seg * 4), Kt + (long)row * ND + d0 + seg * 4);
            }
            cp_commit();
        };

        load_stage(0, 0);
        const int nit = ND / 32;  // 16
        for (int it = 0; it < nit; ++it) {
            if (it + 1 < nit) {
                load_stage((it + 1) & 1, (it + 1) * 32);
                asm volatile("cp.async.wait_group 1;" ::: "memory");
            } else {
                asm volatile("cp.async.wait_group 0;" ::: "memory");
            }
            __syncthreads();
            const float* qs = Qs + (it & 1) * Q_STAGE;
            const float* ks = Ks + (it & 1) * Q_STAGE;
#pragma unroll
            for (int kk = 0; kk < 32; kk += 8) {
                uint32_t af[4][4], bf[8][2];
#pragma unroll
                for (int mt = 0; mt < 4; mt++) {
                    const float* ar = qs + (wm + mt * 16 + g) * ASTR + kk + qd;
                    af[mt][0] = __float_as_uint(ar[0]);
                    af[mt][1] = __float_as_uint(ar[8 * ASTR]);
                    af[mt][2] = __float_as_uint(ar[4]);
                    af[mt][3] = __float_as_uint(ar[8 * ASTR + 4]);
                }
#pragma unroll
                for (int nt = 0; nt < 8; nt++) {
                    const float* br = ks + (wn + nt * 8 + g) * ASTR + kk + qd;
                    bf[nt][0] = __float_as_uint(br[0]);
                    bf[nt][1] = __float_as_uint(br[4]);
                }
#pragma unroll
                for (int mt = 0; mt < 4; mt++)
#pragma unroll
                    for (int nt = 0; nt < 8; nt++) mma_tf32(acc[mt][nt], af[mt], bf[nt]);
            }
            __syncthreads();
        }

        // epilogue for this 128x128 key tile
#pragma unroll
        for (int mt = 0; mt < 4; mt++) {
            long r0 = (long)b * NS + q0 + wm + mt * 16 + g;
#pragma unroll
            for (int nt = 0; nt < 8; nt++) {
                int kc = kt * 128 + wn + nt * 8 + 2 * qd;
                long off0 = r0 * NS + kc;
                int2 dA = *(const int2*)(dep + off0);
                float e0 = dA.x ? __expf(acc[mt][nt][0] * dtab[dA.x]) : 0.f;
                float e1 = dA.y ? __expf(acc[mt][nt][1] * dtab[dA.y]) : 0.f;
                *(float2*)(Wout + off0) = make_float2(e0, e1);
                rs[mt][0] += e0 + e1;
                long off1 = (r0 + 8) * NS + kc;
                int2 dB = *(const int2*)(dep + off1);
                float e2 = dB.x ? __expf(acc[mt][nt][2] * dtab[dB.x]) : 0.f;
                float e3 = dB.y ? __expf(acc[mt][nt][3] * dtab[dB.y]) : 0.f;
                *(float2*)(Wout + off1) = make_float2(e2, e3);
                rs[mt][1] += e2 + e3;
            }
        }
    }

    // reduce rowsums: over qd lanes, then across the two wn-half warps via smem
#pragma unroll
    for (int mt = 0; mt < 4; mt++) {
        rs[mt][0] += __shfl_xor_sync(0xffffffff, rs[mt][0], 1);
        rs[mt][0] += __shfl_xor_sync(0xffffffff, rs[mt][0], 2);
        rs[mt][1] += __shfl_xor_sync(0xffffffff, rs[mt][1], 1);
        rs[mt][1] += __shfl_xor_sync(0xffffffff, rs[mt][1], 2);
    }
    if (qd == 0) {
#pragma unroll
        for (int mt = 0; mt < 4; mt++) {
            rs2[(warp & 1) * 128 + wm + mt * 16 + g] = rs[mt][0];
            rs2[(warp & 1) * 128 + wm + mt * 16 + g + 8] = rs[mt][1];
        }
    }
    __syncthreads();
    // 128 threads: combine wn halves, write partial (per key-half) rowsum
    rowsum2[(long)half * BSROWS + (long)b * NS + q0 + tid] = rs2[tid] + rs2[128 + tid];
}

// ---------------------------------------------------------------------------
// 4) normalize weights in place
// ---------------------------------------------------------------------------
__global__ void normalize_kernel(float* __restrict__ W, const float* __restrict__ rs2) {
    long i = ((long)blockIdx.x * 256 + threadIdx.x) * 4;
    long row = i >> 10;
    float r = __frcp_rn(rs2[row] + rs2[BSROWS + row]);
    float4 v = *(float4*)(W + i);
    v.x *= r; v.y *= r; v.z *= r; v.w *= r;
    *(float4*)(W + i) = v;
}

// ---------------------------------------------------------------------------
// launch
// ---------------------------------------------------------------------------
extern "C" void kernel_launch(void* const* d_in, const int* in_sizes, int n_in,
                              void* d_out, int out_size) {
    const int* inputs      = (const int*)d_in[0];
    const int* dependency  = (const int*)d_in[1];
    const float* embed     = (const float*)d_in[2];
    const float* dep_table = (const float*)d_in[3];
    const float* Wq = (const float*)d_in[4];
    const float* bq = (const float*)d_in[5];
    const float* Wk = (const float*)d_in[6];
    const float* bk = (const float*)d_in[7];
    const float* Wv = (const float*)d_in[8];
    const float* bv = (const float*)d_in[9];
    const float* W1 = (const float*)d_in[10];
    const float* b1 = (const float*)d_in[11];
    const float* W2 = (const float*)d_in[12];
    const float* b2 = (const float*)d_in[13];

    float* out = (float*)d_out;
    float* out_wm = out;          // [B,S,D]
    float* out_w  = out + XSZ;    // [B,S,S]

    float *X, *Qp, *Kp, *Vp, *WM, *H, *WR, *RS;
    cudaGetSymbolAddress((void**)&X, g_X);
    cudaGetSymbolAddress((void**)&Qp, g_Q);
    cudaGetSymbolAddress((void**)&Kp, g_K);
    cudaGetSymbolAddress((void**)&Vp, g_V);
    cudaGetSymbolAddress((void**)&WM, g_WM);
    cudaGetSymbolAddress((void**)&H, g_H);
    cudaGetSymbolAddress((void**)&WR, g_Wr);
    cudaGetSymbolAddress((void**)&RS, g_rowsum2);

    cudaFuncSetAttribute(gemm_pipe<1, false, true>,  cudaFuncAttributeMaxDynamicSharedMemorySize, GEMM_SMEM);
    cudaFuncSetAttribute(gemm_pipe<0, true,  true>,  cudaFuncAttributeMaxDynamicSharedMemorySize, GEMM_SMEM);
    cudaFuncSetAttribute(gemm_pipe<2, false, true>,  cudaFuncAttributeMaxDynamicSharedMemorySize, GEMM_SMEM);
    cudaFuncSetAttribute(gemm_pipe<1, false, false>, cudaFuncAttributeMaxDynamicSharedMemorySize, GEMM_SMEM);
    cudaFuncSetAttribute(scores_pipe, cudaFuncAttributeMaxDynamicSharedMemorySize, SC_SMEM);

    // 0) pre-round weights; 1) gather (rounds X)
    preround5<<<dim3(WELEMS / 1024, 5), 256>>>(Wq, Wk, Wv, W1, W2, WR);
    gather_kernel<<<16384, 128>>>(inputs, embed, X);

    // 2) projections (K=512)
    dim3 gproj(4, 128, 1);
    gemm_pipe<1, false, true><<<gproj, 128, GEMM_SMEM>>>(X, WR + 0L * WELEMS, bq, Qp, 512, 512, 512, 512, 512, 0, 0, 0);
    gemm_pipe<1, false, true><<<gproj, 128, GEMM_SMEM>>>(X, WR + 1L * WELEMS, bk, Kp, 512, 512, 512, 512, 512, 0, 0, 0);
    gemm_pipe<1, false, true><<<gproj, 128, GEMM_SMEM>>>(X, WR + 2L * WELEMS, bv, Vp, 512, 512, 512, 512, 512, 0, 0, 0);

    // 3) scores + exp + mask + partial rowsums
    scores_pipe<<<dim3(8, 2, 16), 128, SC_SMEM>>>(Qp, Kp, dependency, dep_table, out_w, RS);

    // 4) normalize
    normalize_kernel<<<(int)(WSZ / 4 / 256), 256>>>(out_w, RS);

    // 5) wm_raw = weights @ V (batched; A needs in-register tf32 cvt)
    gemm_pipe<0, true, true><<<dim3(4, 8, 16), 128, GEMM_SMEM>>>(
        out_w, Vp, nullptr, WM, 512, 1024, 1024, 512, 512,
        (long)NS * NS, (long)NS * ND, (long)NS * ND);

    // 6) h = tanh(wm @ W1 + b1)
    gemm_pipe<2, false, true><<<gproj, 128, GEMM_SMEM>>>(WM, WR + 3L * WELEMS, b1, H, 512, 512, 512, 512, 512, 0, 0, 0);

    // 7) out = h @ W2 + b2
    gemm_pipe<1, false, false><<<gproj, 128, GEMM_SMEM>>>(H, WR + 4L * WELEMS, b2, out_wm, 512, 512, 512, 512, 512, 0, 0, 0);
}

// round 4
// speedup vs baseline: 1.9164x; 1.0642x over previous
#include <cuda_runtime.h>
#include <cstdint>

#define NB 16
#define NS 1024
#define ND 512

constexpr long BSROWS = 16384;
constexpr long XSZ = BSROWS * 512;        // 8388608
constexpr long WSZ = (long)NB * NS * NS;  // 16777216
constexpr int  WELEMS = 512 * 512;

// Scratch (device globals)
__device__ float g_X[XSZ];
__device__ float g_QKV[3 * XSZ];
__device__ float g_WM[XSZ];
__device__ float g_H[XSZ];
__device__ float g_Wr[5L * WELEMS];
__device__ float g_bias3[3 * 512];
__device__ float g_rsp[8 * BSROWS];   // rowsum partials per key-tile
__device__ float g_rsum[BSROWS];      // total rowsums

// ---------------------------------------------------------------------------
// helpers
// ---------------------------------------------------------------------------
__device__ __forceinline__ float tf32r(float x) {
    uint32_t u;
    asm("cvt.rna.tf32.f32 %0, %1;" : "=r"(u) : "f"(x));
    return __uint_as_float(u);
}
__device__ __forceinline__ void mma_tf32(float* c, const uint32_t* a, const uint32_t* b) {
    asm volatile(
        "mma.sync.aligned.m16n8k8.row.col.f32.tf32.tf32.f32 "
        "{%0,%1,%2,%3},{%4,%5,%6,%7},{%8,%9},{%0,%1,%2,%3};"
        : "+f"(c[0]), "+f"(c[1]), "+f"(c[2]), "+f"(c[3])
        : "r"(a[0]), "r"(a[1]), "r"(a[2]), "r"(a[3]), "r"(b[0]), "r"(b[1]));
}
__device__ __forceinline__ uint32_t s2u(const void* p) {
    return (uint32_t)__cvta_generic_to_shared(p);
}
__device__ __forceinline__ void cpa16(uint32_t dst, const float* src) {
    asm volatile("cp.async.cg.shared.global [%0], [%1], 16;"
                 :: "r"(dst), "l"(__cvta_generic_to_global((const void*)src)));
}
__device__ __forceinline__ void cp_commit() {
    asm volatile("cp.async.commit_group;");
}

// ---------------------------------------------------------------------------
// small prep kernels
// ---------------------------------------------------------------------------
__global__ void preround5(const float* __restrict__ w0, const float* __restrict__ w1,
                          const float* __restrict__ w2, const float* __restrict__ w3,
                          const float* __restrict__ w4, float* __restrict__ out) {
    int z = blockIdx.y;
    const float* src = (z == 0) ? w0 : (z == 1) ? w1 : (z == 2) ? w2 : (z == 3) ? w3 : w4;
    long i = ((long)blockIdx.x * 256 + threadIdx.x) * 4;
    float4 v = *(const float4*)(src + i);
    v.x = tf32r(v.x); v.y = tf32r(v.y); v.z = tf32r(v.z); v.w = tf32r(v.w);
    *(float4*)(out + (long)z * WELEMS + i) = v;
}

__global__ void copy_bias3(const float* __restrict__ bq, const float* __restrict__ bk,
                           const float* __restrict__ bv, float* __restrict__ out) {
    int i = threadIdx.x;
    out[i] = bq[i];
    out[512 + i] = bk[i];
    out[1024 + i] = bv[i];
}

__global__ void gather_kernel(const int* __restrict__ inputs,
                              const float* __restrict__ table,
                              float* __restrict__ X) {
    long row = blockIdx.x;
    long src = (long)inputs[row] * 512;
    float4 v = *(const float4*)(table + src + threadIdx.x * 4);
    v.x = tf32r(v.x); v.y = tf32r(v.y); v.z = tf32r(v.z); v.w = tf32r(v.w);
    *(float4*)(X + row * 512 + threadIdx.x * 4) = v;
}

__global__ void rowsum_total(const float* __restrict__ rsp, float* __restrict__ rsum) {
    long r = (long)blockIdx.x * 256 + threadIdx.x;
    float s = 0.f;
#pragma unroll
    for (int t = 0; t < 8; t++) s += rsp[(long)t * BSROWS + r];
    rsum[r] = s;
}

__global__ void normalize_kernel(float* __restrict__ W, const float* __restrict__ rsum) {
    long i = ((long)blockIdx.x * 256 + threadIdx.x) * 4;
    float r = __frcp_rn(rsum[i >> 10]);
    float4 v = *(float4*)(W + i);
    v.x *= r; v.y *= r; v.z *= r; v.w *= r;
    *(float4*)(W + i) = v;
}

// ---------------------------------------------------------------------------
// 3-stage pipelined tf32 mma.sync GEMM, tile 128x128xBK32, 4 warps (64x64).
// A: [M,K] K-contig.  B: BT ? [N,K] K-contig : [K,N] N-contig.
// EPI: 0 none, 1 +bias, 2 tanh(+bias), 3 scores(dep/exp/mask/rowsum-partials),
//      4 scale rows by 1/rsum (AV on unnormalized weights)
// ---------------------------------------------------------------------------
constexpr int ASTR = 36;                 // floats; row stride of A-style tiles
constexpr int BSTR = 136;                // floats; row stride of [k][n] B tiles
constexpr int STAGE_F = 9216;            // floats per stage (36864 B)
constexpr int SMEM_DYN = 3 * 36864;      // 110592 B

template <int EPI, bool BT, bool CVTA, bool RND>
__global__ __launch_bounds__(128, 2) void gemm3(
    const float* __restrict__ A, const float* __restrict__ B,
    const float* __restrict__ bias, float* __restrict__ C,
    const int* __restrict__ dep, const float* __restrict__ dtab_g,
    float* __restrict__ rsp, const float* __restrict__ rsum,
    int K, int lda, int ldb, int ldc,
    long sA, long sB, long sC, long sBias) {
    extern __shared__ float sm[];
    __shared__ float dtab[64];
    __shared__ float rs2[256];

    const int z = blockIdx.z;
    A += (long)z * sA; B += (long)z * sB; C += (long)z * sC;
    if (EPI == 1 || EPI == 2) bias += (long)z * sBias;

    const int bm = blockIdx.y * 128, bn = blockIdx.x * 128;
    const int tid = threadIdx.x, warp = tid >> 5, lane = tid & 31;
    const int wm = (warp >> 1) * 64, wn = (warp & 1) * 64;
    const int g = lane >> 2, qd = lane & 3;

    if (EPI == 3 && tid < 64) dtab[tid] = dtab_g[tid];

    float acc[4][8][4];
#pragma unroll
    for (int i = 0; i < 4; i++)
#pragma unroll
        for (int j = 0; j < 8; j++)
#pragma unroll
            for (int t = 0; t < 4; t++) acc[i][j][t] = 0.f;

    const int nit = K / 32;
    const uint32_t smb = s2u(sm);

    auto load_stage = [&](int s, int k0) {
        uint32_t abase = smb + s * 36864;
        uint32_t bbase = abase + 18432;
#pragma unroll
        for (int j = 0; j < 8; j++) {
            int c = tid + j * 128;
            int row = c >> 3, seg = c & 7;
            cpa16(abase + row * 144 + seg * 16,
                  A + (long)(bm + row) * lda + k0 + seg * 4);
        }
        if (BT) {
#pragma unroll
            for (int j = 0; j < 8; j++) {
                int c = tid + j * 128;
                int row = c >> 3, seg = c & 7;
                cpa16(bbase + row * 144 + seg * 16,
                      B + (long)(bn + row) * ldb + k0 + seg * 4);
            }
        } else {
#pragma unroll
            for (int j = 0; j < 8; j++) {
                int c = tid + j * 128;
                int kk = c >> 5, seg = c & 31;
                cpa16(bbase + kk * 544 + seg * 16,
                      B + (long)(k0 + kk) * ldb + bn + seg * 4);
            }
        }
    };

    load_stage(0, 0);  cp_commit();
    load_stage(1, 32); cp_commit();

    for (int it = 0; it < nit; ++it) {
        asm volatile("cp.async.wait_group 1;" ::: "memory");
        __syncthreads();
        if (it + 2 < nit) load_stage((it + 2) % 3, (it + 2) * 32);
        cp_commit();

        const float* as = sm + (it % 3) * STAGE_F;
        const float* bs = as + 4608;
#pragma unroll
        for (int ks = 0; ks < 32; ks += 8) {
            uint32_t af[4][4], bf[8][2];
#pragma unroll
            for (int mt = 0; mt < 4; mt++) {
                const float* ar = as + (wm + mt * 16 + g) * ASTR + ks + qd;
                float a0 = ar[0], a1 = ar[8 * ASTR], a2 = ar[4], a3 = ar[8 * ASTR + 4];
                if (CVTA) { a0 = tf32r(a0); a1 = tf32r(a1); a2 = tf32r(a2); a3 = tf32r(a3); }
                af[mt][0] = __float_as_uint(a0); af[mt][1] = __float_as_uint(a1);
                af[mt][2] = __float_as_uint(a2); af[mt][3] = __float_as_uint(a3);
            }
#pragma unroll
            for (int nt = 0; nt < 8; nt++) {
                if (BT) {
                    const float* br = bs + (wn + nt * 8 + g) * ASTR + ks + qd;
                    bf[nt][0] = __float_as_uint(br[0]);
                    bf[nt][1] = __float_as_uint(br[4]);
                } else {
                    bf[nt][0] = __float_as_uint(bs[(ks + qd) * BSTR + wn + nt * 8 + g]);
                    bf[nt][1] = __float_as_uint(bs[(ks + qd + 4) * BSTR + wn + nt * 8 + g]);
                }
            }
#pragma unroll
            for (int mt = 0; mt < 4; mt++)
#pragma unroll
                for (int nt = 0; nt < 8; nt++) mma_tf32(acc[mt][nt], af[mt], bf[nt]);
        }
    }

    // ---------------- epilogue ----------------
    if (EPI == 3) {
        float rsacc[4][2];
#pragma unroll
        for (int mt = 0; mt < 4; mt++) { rsacc[mt][0] = 0.f; rsacc[mt][1] = 0.f; }
#pragma unroll
        for (int mt = 0; mt < 4; mt++) {
            int rl = bm + wm + mt * 16 + g;            // row within batch
#pragma unroll
            for (int nt = 0; nt < 8; nt++) {
                int c0 = bn + wn + nt * 8 + 2 * qd;
                long doff0 = ((long)z * NS + rl) * NS + c0;
                int2 dA = *(const int2*)(dep + doff0);
                float e0 = dA.x ? __expf(acc[mt][nt][0] * dtab[dA.x]) : 0.f;
                float e1 = dA.y ? __expf(acc[mt][nt][1] * dtab[dA.y]) : 0.f;
                *(float2*)(C + (long)rl * ldc + c0) = make_float2(e0, e1);
                rsacc[mt][0] += e0 + e1;
                long doff1 = ((long)z * NS + rl + 8) * NS + c0;
                int2 dB = *(const int2*)(dep + doff1);
                float e2 = dB.x ? __expf(acc[mt][nt][2] * dtab[dB.x]) : 0.f;
                float e3 = dB.y ? __expf(acc[mt][nt][3] * dtab[dB.y]) : 0.f;
                *(float2*)(C + (long)(rl + 8) * ldc + c0) = make_float2(e2, e3);
                rsacc[mt][1] += e2 + e3;
            }
        }
#pragma unroll
        for (int mt = 0; mt < 4; mt++) {
            rsacc[mt][0] += __shfl_xor_sync(0xffffffff, rsacc[mt][0], 1);
            rsacc[mt][0] += __shfl_xor_sync(0xffffffff, rsacc[mt][0], 2);
            rsacc[mt][1] += __shfl_xor_sync(0xffffffff, rsacc[mt][1], 1);
            rsacc[mt][1] += __shfl_xor_sync(0xffffffff, rsacc[mt][1], 2);
        }
        if (qd == 0) {
#pragma unroll
            for (int mt = 0; mt < 4; mt++) {
                rs2[(warp & 1) * 128 + wm + mt * 16 + g] = rsacc[mt][0];
                rs2[(warp & 1) * 128 + wm + mt * 16 + g + 8] = rsacc[mt][1];
            }
        }
        __syncthreads();
        rsp[(long)blockIdx.x * BSROWS + (long)z * NS + bm + tid] = rs2[tid] + rs2[128 + tid];
    } else {
#pragma unroll
        for (int mt = 0; mt < 4; mt++) {
            int rl = bm + wm + mt * 16 + g;
            float r0inv = 1.f, r1inv = 1.f;
            if (EPI == 4) {
                r0inv = __frcp_rn(rsum[(long)z * NS + rl]);
                r1inv = __frcp_rn(rsum[(long)z * NS + rl + 8]);
            }
#pragma unroll
            for (int nt = 0; nt < 8; nt++) {
                int c0 = bn + wn + nt * 8 + 2 * qd;
                float v0 = acc[mt][nt][0], v1 = acc[mt][nt][1];
                float v2 = acc[mt][nt][2], v3 = acc[mt][nt][3];
                if (EPI == 1 || EPI == 2) {
                    float b0 = bias[c0], b1 = bias[c0 + 1];
                    v0 += b0; v1 += b1; v2 += b0; v3 += b1;
                }
                if (EPI == 2) { v0 = tanhf(v0); v1 = tanhf(v1); v2 = tanhf(v2); v3 = tanhf(v3); }
                if (EPI == 4) { v0 *= r0inv; v1 *= r0inv; v2 *= r1inv; v3 *= r1inv; }
                if (RND) { v0 = tf32r(v0); v1 = tf32r(v1); v2 = tf32r(v2); v3 = tf32r(v3); }
                *(float2*)(C + (long)rl * ldc + c0) = make_float2(v0, v1);
                *(float2*)(C + (long)(rl + 8) * ldc + c0) = make_float2(v2, v3);
            }
        }
    }
}

// ---------------------------------------------------------------------------
// launch
// ---------------------------------------------------------------------------
extern "C" void kernel_launch(void* const* d_in, const int* in_sizes, int n_in,
                              void* d_out, int out_size) {
    const int* inputs      = (const int*)d_in[0];
    const int* dependency  = (const int*)d_in[1];
    const float* embed     = (const float*)d_in[2];
    const float* dep_table = (const float*)d_in[3];
    const float* Wq = (const float*)d_in[4];
    const float* bq = (const float*)d_in[5];
    const float* Wk = (const float*)d_in[6];
    const float* bk = (const float*)d_in[7];
    const float* Wv = (const float*)d_in[8];
    const float* bv = (const float*)d_in[9];
    const float* W1 = (const float*)d_in[10];
    const float* b1 = (const float*)d_in[11];
    const float* W2 = (const float*)d_in[12];
    const float* b2 = (const float*)d_in[13];

    float* out = (float*)d_out;
    float* out_wm = out;          // [B,S,D]
    float* out_w  = out + XSZ;    // [B,S,S]

    float *X, *QKV, *WM, *H, *WR, *B3, *RSP, *RSUM;
    cudaGetSymbolAddress((void**)&X, g_X);
    cudaGetSymbolAddress((void**)&QKV, g_QKV);
    cudaGetSymbolAddress((void**)&WM, g_WM);
    cudaGetSymbolAddress((void**)&H, g_H);
    cudaGetSymbolAddress((void**)&WR, g_Wr);
    cudaGetSymbolAddress((void**)&B3, g_bias3);
    cudaGetSymbolAddress((void**)&RSP, g_rsp);
    cudaGetSymbolAddress((void**)&RSUM, g_rsum);

    float* Qp = QKV;
    float* Kp = QKV + XSZ;
    float* Vp = QKV + 2 * XSZ;

    cudaFuncSetAttribute(gemm3<1, false, false, true>,  cudaFuncAttributeMaxDynamicSharedMemorySize, SMEM_DYN);
    cudaFuncSetAttribute(gemm3<3, true,  false, false>, cudaFuncAttributeMaxDynamicSharedMemorySize, SMEM_DYN);
    cudaFuncSetAttribute(gemm3<4, false, true,  true>,  cudaFuncAttributeMaxDynamicSharedMemorySize, SMEM_DYN);
    cudaFuncSetAttribute(gemm3<2, false, false, true>,  cudaFuncAttributeMaxDynamicSharedMemorySize, SMEM_DYN);
    cudaFuncSetAttribute(gemm3<1, false, false, false>, cudaFuncAttributeMaxDynamicSharedMemorySize, SMEM_DYN);

    // prep
    preround5<<<dim3(WELEMS / 1024, 5), 256>>>(Wq, Wk, Wv, W1, W2, WR);
    copy_bias3<<<1, 512>>>(bq, bk, bv, B3);
    gather_kernel<<<16384, 128>>>(inputs, embed, X);

    // QKV fused: z picks weight plane / bias slice / output plane
    gemm3<1, false, false, true><<<dim3(4, 128, 3), 128, SMEM_DYN>>>(
        X, WR, B3, QKV, nullptr, nullptr, nullptr, nullptr,
        512, 512, 512, 512, 0, WELEMS, XSZ, 512);

    // scores: unnormalized e -> out_w, partial rowsums
    gemm3<3, true, false, false><<<dim3(8, 8, 16), 128, SMEM_DYN>>>(
        Qp, Kp, nullptr, out_w, dependency, dep_table, RSP, nullptr,
        512, 512, 512, 1024, (long)NS * ND, (long)NS * ND, (long)NS * NS, 0);

    rowsum_total<<<64, 256>>>(RSP, RSUM);

    // AV on unnormalized weights; epilogue scales rows by 1/rowsum
    gemm3<4, false, true, true><<<dim3(4, 8, 16), 128, SMEM_DYN>>>(
        out_w, Vp, nullptr, WM, nullptr, nullptr, nullptr, RSUM,
        1024, 1024, 512, 512, (long)NS * NS, (long)NS * ND, (long)NS * ND, 0);

    // normalize weights output in place
    normalize_kernel<<<(int)(WSZ / 1024), 256>>>(out_w, RSUM);

    // FFN
    dim3 gproj(4, 128, 1);
    gemm3<2, false, false, true><<<gproj, 128, SMEM_DYN>>>(
        WM, WR + 3L * WELEMS, b1, H, nullptr, nullptr, nullptr, nullptr,
        512, 512, 512, 512, 0, 0, 0, 0);
    gemm3<1, false, false, false><<<gproj, 128, SMEM_DYN>>>(
        H, WR + 4L * WELEMS, b2, out_wm, nullptr, nullptr, nullptr, nullptr,
        512, 512, 512, 512, 0, 0, 0, 0);
}

// round 5
// speedup vs baseline: 3.1106x; 1.6232x over previous
#include <cuda_runtime.h>
#include <cuda_fp16.h>
#include <cstdint>

#define NB 16
#define NS 1024
#define ND 512

constexpr long BSROWS = 16384;
constexpr long XSZ = BSROWS * 512;        // 8388608
constexpr long WSZ = (long)NB * NS * NS;  // 16777216
constexpr int  WELEMS = 512 * 512;

// Scratch (device globals)
__device__ __half g_Xh[XSZ];
__device__ __half g_QKVh[3 * XSZ];
__device__ __half g_Vth[XSZ];
__device__ __half g_Eh[WSZ];
__device__ __half g_WMh[XSZ];
__device__ __half g_Hh[XSZ];
__device__ __half g_Wth[5L * WELEMS];
__device__ float  g_bias3[3 * 512];
__device__ float  g_rsp[8 * BSROWS];
__device__ float  g_rsum[BSROWS];

// ---------------------------------------------------------------------------
// helpers
// ---------------------------------------------------------------------------
__device__ __forceinline__ uint32_t s2u(const void* p) {
    return (uint32_t)__cvta_generic_to_shared(p);
}
__device__ __forceinline__ void cpa16(uint32_t dst, const void* src) {
    asm volatile("cp.async.cg.shared.global [%0], [%1], 16;"
                 :: "r"(dst), "l"(__cvta_generic_to_global(src)));
}
__device__ __forceinline__ void cp_commit() {
    asm volatile("cp.async.commit_group;");
}
__device__ __forceinline__ void mma_f16(float* c, const uint32_t* a,
                                        uint32_t b0, uint32_t b1) {
    asm volatile(
        "mma.sync.aligned.m16n8k16.row.col.f32.f16.f16.f32 "
        "{%0,%1,%2,%3},{%4,%5,%6,%7},{%8,%9},{%0,%1,%2,%3};"
        : "+f"(c[0]), "+f"(c[1]), "+f"(c[2]), "+f"(c[3])
        : "r"(a[0]), "r"(a[1]), "r"(a[2]), "r"(a[3]), "r"(b0), "r"(b1));
}
#define LDSM4(r0, r1, r2, r3, addr) \
    asm volatile("ldmatrix.sync.aligned.m8n8.x4.shared.b16 {%0,%1,%2,%3}, [%4];" \
                 : "=r"(r0), "=r"(r1), "=r"(r2), "=r"(r3) : "r"(addr))

// ---------------------------------------------------------------------------
// prep kernels
// ---------------------------------------------------------------------------
// weights: transpose + fp16:  Wt[z][n][k] = h(W_z[k][n])
__global__ void preroundTh(const float* __restrict__ w0, const float* __restrict__ w1,
                           const float* __restrict__ w2, const float* __restrict__ w3,
                           const float* __restrict__ w4, __half* __restrict__ out) {
    __shared__ float t[32][33];
    int z = blockIdx.z;
    const float* W = (z == 0) ? w0 : (z == 1) ? w1 : (z == 2) ? w2 : (z == 3) ? w3 : w4;
    int n0 = blockIdx.x * 32, k0 = blockIdx.y * 32;
    int tx = threadIdx.x, ty = threadIdx.y;
#pragma unroll
    for (int i = 0; i < 32; i += 8)
        t[ty + i][tx] = W[(long)(k0 + ty + i) * 512 + n0 + tx];
    __syncthreads();
#pragma unroll
    for (int i = 0; i < 32; i += 8)
        out[(long)z * WELEMS + (long)(n0 + ty + i) * 512 + k0 + tx] =
            __float2half_rn(t[tx][ty + i]);
}

__global__ void copy_bias3(const float* __restrict__ bq, const float* __restrict__ bk,
                           const float* __restrict__ bv, float* __restrict__ out) {
    int i = threadIdx.x;
    out[i] = bq[i];
    out[512 + i] = bk[i];
    out[1024 + i] = bv[i];
}

__global__ void gather_h(const int* __restrict__ inputs,
                         const float* __restrict__ table,
                         __half* __restrict__ X) {
    long row = blockIdx.x;
    long src = (long)inputs[row] * 512;
    float4 v = *(const float4*)(table + src + threadIdx.x * 4);
    __half2 h0 = __floats2half2_rn(v.x, v.y);
    __half2 h1 = __floats2half2_rn(v.z, v.w);
    uint2 st;
    st.x = *(uint32_t*)&h0;
    st.y = *(uint32_t*)&h1;
    *(uint2*)(X + row * 512 + threadIdx.x * 4) = st;
}

// V transpose (fp16): Vt[b][d][s] = V[b][s][d]
__global__ void transVh(const __half* __restrict__ V, __half* __restrict__ Vt) {
    __shared__ __half t[32][33];
    int b = blockIdx.z;
    int d0 = blockIdx.x * 32, s0 = blockIdx.y * 32;
    const __half* Vb = V + (long)b * NS * ND;
    __half* Vtb = Vt + (long)b * NS * ND;
    int tx = threadIdx.x, ty = threadIdx.y;
#pragma unroll
    for (int i = 0; i < 32; i += 8)
        t[ty + i][tx] = Vb[(long)(s0 + ty + i) * ND + d0 + tx];
    __syncthreads();
#pragma unroll
    for (int i = 0; i < 32; i += 8)
        Vtb[(long)(d0 + ty + i) * NS + s0 + tx] = t[tx][ty + i];
}

__global__ void rowsum_total(const float* __restrict__ rsp, float* __restrict__ rsum) {
    long r = (long)blockIdx.x * 256 + threadIdx.x;
    float s = 0.f;
#pragma unroll
    for (int t = 0; t < 8; t++) s += rsp[(long)t * BSROWS + r];
    rsum[r] = s;
}

__global__ void normalize_kernel(float* __restrict__ W, const float* __restrict__ rsum) {
    long i = ((long)blockIdx.x * 256 + threadIdx.x) * 4;
    float r = __frcp_rn(rsum[i >> 10]);
    float4 v = *(float4*)(W + i);
    v.x *= r; v.y *= r; v.z *= r; v.w *= r;
    *(float4*)(W + i) = v;
}

// ---------------------------------------------------------------------------
// fp16 GEMM via ldmatrix + mma.m16n8k16, fp32 accum.
// CTA tile 128x128, BK=64 halfs, 3-stage cp.async, 4 warps (64x64 each).
// A: [M][K] k-contig fp16.  B: [N][K] k-contig fp16 (always "BT").
// EPI: 1 +bias, 2 tanh(+bias), 3 scores (dep/exp/mask/rowsum, dual out),
//      4 scale rows by 1/rsum.
// OUTH: write fp16 C (else fp32).
// smem per stage: A 128x144B + B 128x144B = 36864B; 3 stages.
// ---------------------------------------------------------------------------
constexpr int STAGE_B = 36864;
constexpr int SMEM_DYN = 3 * STAGE_B;   // 110592

template <int EPI, bool OUTH>
__global__ __launch_bounds__(128, 2) void gemm_h(
    const __half* __restrict__ A, const __half* __restrict__ B,
    const float* __restrict__ bias, void* __restrict__ Cv,
    __half* __restrict__ Eh,
    const int* __restrict__ dep, const float* __restrict__ dtab_g,
    float* __restrict__ rsp, const float* __restrict__ rsum,
    int K, int lda, int ldb, int ldc,
    long sA, long sB, long sC, long sBias) {
    extern __shared__ char smraw[];
    __shared__ float dtab[64];
    __shared__ float rs2[256];

    const int z = blockIdx.z;
    A += (long)z * sA;
    B += (long)z * sB;
    float* Cf = (float*)Cv + (OUTH ? 0 : (long)z * sC);
    __half* Ch = (__half*)Cv + (OUTH ? (long)z * sC : 0);
    if (EPI == 1 || EPI == 2) bias += (long)z * sBias;
    if (EPI == 3) Eh += (long)z * NS * NS;

    const int bm = blockIdx.y * 128, bn = blockIdx.x * 128;
    const int tid = threadIdx.x, warp = tid >> 5, lane = tid & 31;
    const int wm = (warp >> 1) * 64, wn = (warp & 1) * 64;
    const int g = lane >> 2, qd = lane & 3;

    if (EPI == 3 && tid < 64) dtab[tid] = dtab_g[tid];

    float acc[4][8][4];
#pragma unroll
    for (int i = 0; i < 4; i++)
#pragma unroll
        for (int j = 0; j < 8; j++)
#pragma unroll
            for (int t = 0; t < 4; t++) acc[i][j][t] = 0.f;

    const int nit = K / 64;
    const uint32_t smb = s2u(smraw);

    // ldmatrix per-thread offsets (bytes within stage)
    const uint32_t aoff = (uint32_t)((wm + (lane & 15)) * 144 + (lane >> 4) * 16);
    const uint32_t boff = (uint32_t)(18432 +
        (wn + (lane & 7) + ((lane >> 4) & 1) * 8) * 144 + ((lane >> 3) & 1) * 16);

    auto load_stage = [&](int s, int k0) {
        uint32_t abase = smb + s * STAGE_B;
        uint32_t bbase = abase + 18432;
#pragma unroll
        for (int j = 0; j < 8; j++) {
            int c = tid + j * 128;
            int row = c >> 3, ch = c & 7;
            cpa16(abase + row * 144 + ch * 16,
                  A + (long)(bm + row) * lda + k0 + ch * 8);
        }
#pragma unroll
        for (int j = 0; j < 8; j++) {
            int c = tid + j * 128;
            int row = c >> 3, ch = c & 7;
            cpa16(bbase + row * 144 + ch * 16,
                  B + (long)(bn + row) * ldb + k0 + ch * 8);
        }
    };

    auto ldsm_step = [&](uint32_t sbase, int s, uint32_t af[4][4], uint32_t bf[4][4]) {
#pragma unroll
        for (int mt = 0; mt < 4; mt++)
            LDSM4(af[mt][0], af[mt][1], af[mt][2], af[mt][3],
                  sbase + aoff + mt * 2304 + s * 32);
#pragma unroll
        for (int np = 0; np < 4; np++)
            LDSM4(bf[np][0], bf[np][1], bf[np][2], bf[np][3],
                  sbase + boff + np * 2304 + s * 32);
    };

    load_stage(0, 0);  cp_commit();
    load_stage(1, 64); cp_commit();

    for (int it = 0; it < nit; ++it) {
        asm volatile("cp.async.wait_group 1;" ::: "memory");
        __syncthreads();
        if (it + 2 < nit) load_stage((it + 2) % 3, (it + 2) * 64);
        cp_commit();

        const uint32_t sbase = smb + (it % 3) * STAGE_B;
        uint32_t af[2][4][4], bf[2][4][4];
        ldsm_step(sbase, 0, af[0], bf[0]);
#pragma unroll
        for (int s = 0; s < 4; s++) {
            if (s < 3) ldsm_step(sbase, s + 1, af[(s + 1) & 1], bf[(s + 1) & 1]);
            const uint32_t (*a)[4] = af[s & 1];
            const uint32_t (*b)[4] = bf[s & 1];
#pragma unroll
            for (int mt = 0; mt < 4; mt++)
#pragma unroll
                for (int nt = 0; nt < 8; nt++)
                    mma_f16(acc[mt][nt], a[mt],
                            b[nt >> 1][(nt & 1) * 2], b[nt >> 1][(nt & 1) * 2 + 1]);
        }
    }

    // ---------------- epilogue ----------------
    if (EPI == 3) {
        float rsacc[4][2];
#pragma unroll
        for (int mt = 0; mt < 4; mt++) { rsacc[mt][0] = 0.f; rsacc[mt][1] = 0.f; }
#pragma unroll
        for (int mt = 0; mt < 4; mt++) {
            int rl = bm + wm + mt * 16 + g;
#pragma unroll
            for (int nt = 0; nt < 8; nt++) {
                int c0 = bn + wn + nt * 8 + 2 * qd;
                long doff0 = ((long)z * NS + rl) * NS + c0;
                int2 dA = *(const int2*)(dep + doff0);
                float e0 = dA.x ? __expf(acc[mt][nt][0] * dtab[dA.x]) : 0.f;
                float e1 = dA.y ? __expf(acc[mt][nt][1] * dtab[dA.y]) : 0.f;
                *(float2*)(Cf + (long)rl * ldc + c0) = make_float2(e0, e1);
                __half2 h0 = __floats2half2_rn(e0, e1);
                *(__half2*)(Eh + (long)rl * NS + c0) = h0;
                rsacc[mt][0] += e0 + e1;
                long doff1 = ((long)z * NS + rl + 8) * NS + c0;
                int2 dB = *(const int2*)(dep + doff1);
                float e2 = dB.x ? __expf(acc[mt][nt][2] * dtab[dB.x]) : 0.f;
                float e3 = dB.y ? __expf(acc[mt][nt][3] * dtab[dB.y]) : 0.f;
                *(float2*)(Cf + (long)(rl + 8) * ldc + c0) = make_float2(e2, e3);
                __half2 h1 = __floats2half2_rn(e2, e3);
                *(__half2*)(Eh + (long)(rl + 8) * NS + c0) = h1;
                rsacc[mt][1] += e2 + e3;
            }
        }
#pragma unroll
        for (int mt = 0; mt < 4; mt++) {
            rsacc[mt][0] += __shfl_xor_sync(0xffffffff, rsacc[mt][0], 1);
            rsacc[mt][0] += __shfl_xor_sync(0xffffffff, rsacc[mt][0], 2);
            rsacc[mt][1] += __shfl_xor_sync(0xffffffff, rsacc[mt][1], 1);
            rsacc[mt][1] += __shfl_xor_sync(0xffffffff, rsacc[mt][1], 2);
        }
        if (qd == 0) {
#pragma unroll
            for (int mt = 0; mt < 4; mt++) {
                rs2[(warp & 1) * 128 + wm + mt * 16 + g] = rsacc[mt][0];
                rs2[(warp & 1) * 128 + wm + mt * 16 + g + 8] = rsacc[mt][1];
            }
        }
        __syncthreads();
        rsp[(long)blockIdx.x * BSROWS + (long)z * NS + bm + tid] = rs2[tid] + rs2[128 + tid];
    } else {
#pragma unroll
        for (int mt = 0; mt < 4; mt++) {
            int rl = bm + wm + mt * 16 + g;
            float r0inv = 1.f, r1inv = 1.f;
            if (EPI == 4) {
                r0inv = __frcp_rn(rsum[(long)z * NS + rl]);
                r1inv = __frcp_rn(rsum[(long)z * NS + rl + 8]);
            }
#pragma unroll
            for (int nt = 0; nt < 8; nt++) {
                int c0 = bn + wn + nt * 8 + 2 * qd;
                float v0 = acc[mt][nt][0], v1 = acc[mt][nt][1];
                float v2 = acc[mt][nt][2], v3 = acc[mt][nt][3];
                if (EPI == 1 || EPI == 2) {
                    float b0 = bias[c0], b1 = bias[c0 + 1];
                    v0 += b0; v1 += b1; v2 += b0; v3 += b1;
                }
                if (EPI == 2) { v0 = tanhf(v0); v1 = tanhf(v1); v2 = tanhf(v2); v3 = tanhf(v3); }
                if (EPI == 4) { v0 *= r0inv; v1 *= r0inv; v2 *= r1inv; v3 *= r1inv; }
                if (OUTH) {
                    __half2 h0 = __floats2half2_rn(v0, v1);
                    __half2 h1 = __floats2half2_rn(v2, v3);
                    *(__half2*)(Ch + (long)rl * ldc + c0) = h0;
                    *(__half2*)(Ch + (long)(rl + 8) * ldc + c0) = h1;
                } else {
                    *(float2*)(Cf + (long)rl * ldc + c0) = make_float2(v0, v1);
                    *(float2*)(Cf + (long)(rl + 8) * ldc + c0) = make_float2(v2, v3);
                }
            }
        }
    }
}

// ---------------------------------------------------------------------------
// launch
// ---------------------------------------------------------------------------
extern "C" void kernel_launch(void* const* d_in, const int* in_sizes, int n_in,
                              void* d_out, int out_size) {
    const int* inputs      = (const int*)d_in[0];
    const int* dependency  = (const int*)d_in[1];
    const float* embed     = (const float*)d_in[2];
    const float* dep_table = (const float*)d_in[3];
    const float* Wq = (const float*)d_in[4];
    const float* bq = (const float*)d_in[5];
    const float* Wk = (const float*)d_in[6];
    const float* bk = (const float*)d_in[7];
    const float* Wv = (const float*)d_in[8];
    const float* bv = (const float*)d_in[9];
    const float* W1 = (const float*)d_in[10];
    const float* b1 = (const float*)d_in[11];
    const float* W2 = (const float*)d_in[12];
    const float* b2 = (const float*)d_in[13];

    float* out = (float*)d_out;
    float* out_wm = out;          // [B,S,D]
    float* out_w  = out + XSZ;    // [B,S,S]

    __half *Xh, *QKVh, *Vth, *Eh, *WMh, *Hh, *Wth;
    float *B3, *RSP, *RSUM;
    cudaGetSymbolAddress((void**)&Xh, g_Xh);
    cudaGetSymbolAddress((void**)&QKVh, g_QKVh);
    cudaGetSymbolAddress((void**)&Vth, g_Vth);
    cudaGetSymbolAddress((void**)&Eh, g_Eh);
    cudaGetSymbolAddress((void**)&WMh, g_WMh);
    cudaGetSymbolAddress((void**)&Hh, g_Hh);
    cudaGetSymbolAddress((void**)&Wth, g_Wth);
    cudaGetSymbolAddress((void**)&B3, g_bias3);
    cudaGetSymbolAddress((void**)&RSP, g_rsp);
    cudaGetSymbolAddress((void**)&RSUM, g_rsum);

    __half* Qh = QKVh;
    __half* Kh = QKVh + XSZ;
    __half* Vh = QKVh + 2 * XSZ;

    cudaFuncSetAttribute(gemm_h<1, true>,  cudaFuncAttributeMaxDynamicSharedMemorySize, SMEM_DYN);
    cudaFuncSetAttribute(gemm_h<3, false>, cudaFuncAttributeMaxDynamicSharedMemorySize, SMEM_DYN);
    cudaFuncSetAttribute(gemm_h<4, true>,  cudaFuncAttributeMaxDynamicSharedMemorySize, SMEM_DYN);
    cudaFuncSetAttribute(gemm_h<2, true>,  cudaFuncAttributeMaxDynamicSharedMemorySize, SMEM_DYN);
    cudaFuncSetAttribute(gemm_h<1, false>, cudaFuncAttributeMaxDynamicSharedMemorySize, SMEM_DYN);

    // prep
    preroundTh<<<dim3(16, 16, 5), dim3(32, 8)>>>(Wq, Wk, Wv, W1, W2, Wth);
    copy_bias3<<<1, 512>>>(bq, bk, bv, B3);
    gather_h<<<16384, 128>>>(inputs, embed, Xh);

    // QKV fused (fp16 out): z picks weight plane / bias slice / output plane
    gemm_h<1, true><<<dim3(4, 128, 3), 128, SMEM_DYN>>>(
        Xh, Wth, B3, QKVh, nullptr, nullptr, nullptr, nullptr, nullptr,
        512, 512, 512, 512, 0, WELEMS, XSZ, 512);

    // V transpose (fp16)
    transVh<<<dim3(16, 32, 16), dim3(32, 8)>>>(Vh, Vth);

    // scores: S = Q K^T; exp/mask; fp32 -> out_w, fp16 -> Eh; partial rowsums
    gemm_h<3, false><<<dim3(8, 8, 16), 128, SMEM_DYN>>>(
        Qh, Kh, nullptr, out_w, Eh, dependency, dep_table, RSP, nullptr,
        512, 512, 512, 1024, (long)NS * ND, (long)NS * ND, (long)NS * NS, 0);

    rowsum_total<<<64, 256>>>(RSP, RSUM);

    // AV on unnormalized Eh; epilogue scales rows by 1/rowsum; fp16 out
    gemm_h<4, true><<<dim3(4, 8, 16), 128, SMEM_DYN>>>(
        Eh, Vth, nullptr, WMh, nullptr, nullptr, nullptr, nullptr, RSUM,
        1024, 1024, 1024, 512, (long)NS * NS, (long)NS * ND, (long)NS * ND, 0);

    // normalize weights output in place (fp32)
    normalize_kernel<<<(int)(WSZ / 1024), 256>>>(out_w, RSUM);

    // FFN
    dim3 gproj(4, 128, 1);
    gemm_h<2, true><<<gproj, 128, SMEM_DYN>>>(
        WMh, Wth + 3L * WELEMS, b1, Hh, nullptr, nullptr, nullptr, nullptr, nullptr,
        512, 512, 512, 512, 0, 0, 0, 0);
    gemm_h<1, false><<<gproj, 128, SMEM_DYN>>>(
        Hh, Wth + 4L * WELEMS, b2, out_wm, nullptr, nullptr, nullptr, nullptr, nullptr,
        512, 512, 512, 512, 0, 0, 0, 0);
}

// round 6
// speedup vs baseline: 3.2517x; 1.0454x over previous
#include <cuda_runtime.h>
#include <cuda_fp16.h>
#include <cstdint>

#define NB 16
#define NS 1024
#define ND 512

constexpr long BSROWS = 16384;
constexpr long XSZ = BSROWS * 512;        // 8388608
constexpr long WSZ = (long)NB * NS * NS;  // 16777216
constexpr int  WELEMS = 512 * 512;

// Scratch (device globals)
__device__ __half g_Xh[XSZ];
__device__ __half g_QKVh[3 * XSZ];
__device__ __half g_Vth[XSZ];
__device__ __half g_Eh[WSZ];
__device__ __half g_WMh[XSZ];
__device__ __half g_Hh[XSZ];
__device__ __half g_Wth[5L * WELEMS];
__device__ float  g_bias3[3 * 512];
__device__ float  g_rsp[8 * BSROWS];
__device__ float  g_rsum[BSROWS];

// ---------------------------------------------------------------------------
// helpers
// ---------------------------------------------------------------------------
__device__ __forceinline__ uint32_t s2u(const void* p) {
    return (uint32_t)__cvta_generic_to_shared(p);
}
__device__ __forceinline__ void cpa16(uint32_t dst, const void* src) {
    asm volatile("cp.async.cg.shared.global [%0], [%1], 16;"
                 :: "r"(dst), "l"(__cvta_generic_to_global(src)));
}
__device__ __forceinline__ void cp_commit() {
    asm volatile("cp.async.commit_group;");
}
__device__ __forceinline__ void mma_f16(float* c, const uint32_t* a,
                                        uint32_t b0, uint32_t b1) {
    asm volatile(
        "mma.sync.aligned.m16n8k16.row.col.f32.f16.f16.f32 "
        "{%0,%1,%2,%3},{%4,%5,%6,%7},{%8,%9},{%0,%1,%2,%3};"
        : "+f"(c[0]), "+f"(c[1]), "+f"(c[2]), "+f"(c[3])
        : "r"(a[0]), "r"(a[1]), "r"(a[2]), "r"(a[3]), "r"(b0), "r"(b1));
}
#define LDSM4(r0, r1, r2, r3, addr) \
    asm volatile("ldmatrix.sync.aligned.m8n8.x4.shared.b16 {%0,%1,%2,%3}, [%4];" \
                 : "=r"(r0), "=r"(r1), "=r"(r2), "=r"(r3) : "r"(addr))

// ---------------------------------------------------------------------------
// prep kernels
// ---------------------------------------------------------------------------
__global__ void preroundTh(const float* __restrict__ w0, const float* __restrict__ w1,
                           const float* __restrict__ w2, const float* __restrict__ w3,
                           const float* __restrict__ w4, __half* __restrict__ out) {
    __shared__ float t[32][33];
    int z = blockIdx.z;
    const float* W = (z == 0) ? w0 : (z == 1) ? w1 : (z == 2) ? w2 : (z == 3) ? w3 : w4;
    int n0 = blockIdx.x * 32, k0 = blockIdx.y * 32;
    int tx = threadIdx.x, ty = threadIdx.y;
#pragma unroll
    for (int i = 0; i < 32; i += 8)
        t[ty + i][tx] = W[(long)(k0 + ty + i) * 512 + n0 + tx];
    __syncthreads();
#pragma unroll
    for (int i = 0; i < 32; i += 8)
        out[(long)z * WELEMS + (long)(n0 + ty + i) * 512 + k0 + tx] =
            __float2half_rn(t[tx][ty + i]);
}

__global__ void copy_bias3(const float* __restrict__ bq, const float* __restrict__ bk,
                           const float* __restrict__ bv, float* __restrict__ out) {
    int i = threadIdx.x;
    out[i] = bq[i];
    out[512 + i] = bk[i];
    out[1024 + i] = bv[i];
}

__global__ void gather_h(const int* __restrict__ inputs,
                         const float* __restrict__ table,
                         __half* __restrict__ X) {
    long row = blockIdx.x;
    long src = (long)inputs[row] * 512;
    float4 v = *(const float4*)(table + src + threadIdx.x * 4);
    __half2 h0 = __floats2half2_rn(v.x, v.y);
    __half2 h1 = __floats2half2_rn(v.z, v.w);
    uint2 st;
    st.x = *(uint32_t*)&h0;
    st.y = *(uint32_t*)&h1;
    *(uint2*)(X + row * 512 + threadIdx.x * 4) = st;
}

__global__ void transVh(const __half* __restrict__ V, __half* __restrict__ Vt) {
    __shared__ __half t[32][33];
    int b = blockIdx.z;
    int d0 = blockIdx.x * 32, s0 = blockIdx.y * 32;
    const __half* Vb = V + (long)b * NS * ND;
    __half* Vtb = Vt + (long)b * NS * ND;
    int tx = threadIdx.x, ty = threadIdx.y;
#pragma unroll
    for (int i = 0; i < 32; i += 8)
        t[ty + i][tx] = Vb[(long)(s0 + ty + i) * ND + d0 + tx];
    __syncthreads();
#pragma unroll
    for (int i = 0; i < 32; i += 8)
        Vtb[(long)(d0 + ty + i) * NS + s0 + tx] = t[tx][ty + i];
}

__global__ void rowsum_total(const float* __restrict__ rsp, float* __restrict__ rsum) {
    long r = (long)blockIdx.x * 256 + threadIdx.x;
    float s = 0.f;
#pragma unroll
    for (int t = 0; t < 8; t++) s += rsp[(long)t * BSROWS + r];
    rsum[r] = s;
}

__global__ void normalize_kernel(float* __restrict__ W, const float* __restrict__ rsum) {
    long i = ((long)blockIdx.x * 256 + threadIdx.x) * 4;
    float r = __frcp_rn(rsum[i >> 10]);
    float4 v = *(float4*)(W + i);
    v.x *= r; v.y *= r; v.z *= r; v.w *= r;
    *(float4*)(W + i) = v;
}

// ---------------------------------------------------------------------------
// fp16 GEMM via ldmatrix + mma.m16n8k16, fp32 accum.
// CTA tile 128x128, BK=64 halfs, 3-stage cp.async, 256 threads = 8 warps,
// warp tile 32x64 (4m x 2n warp grid). 2 CTAs/SM -> 16 warps/SM.
// A: [M][K] k-contig fp16.  B: [N][K] k-contig fp16.
// EPI: 1 +bias, 2 tanh(+bias), 3 scores (dep/exp/mask/rowsum, dual out),
//      4 scale rows by 1/rsum.  OUTH: fp16 C (else fp32).
// ---------------------------------------------------------------------------
constexpr int STAGE_B = 36864;
constexpr int SMEM_DYN = 3 * STAGE_B;   // 110592

template <int EPI, bool OUTH>
__global__ __launch_bounds__(256, 2) void gemm_h(
    const __half* __restrict__ A, const __half* __restrict__ B,
    const float* __restrict__ bias, void* __restrict__ Cv,
    __half* __restrict__ Eh,
    const int* __restrict__ dep, const float* __restrict__ dtab_g,
    float* __restrict__ rsp, const float* __restrict__ rsum,
    int K, int lda, int ldb, int ldc,
    long sA, long sB, long sC, long sBias) {
    extern __shared__ char smraw[];
    __shared__ float dtab[64];
    __shared__ float rs2[256];

    const int z = blockIdx.z;
    A += (long)z * sA;
    B += (long)z * sB;
    float* Cf = (float*)Cv + (OUTH ? 0 : (long)z * sC);
    __half* Ch = (__half*)Cv + (OUTH ? (long)z * sC : 0);
    if (EPI == 1 || EPI == 2) bias += (long)z * sBias;
    if (EPI == 3) Eh += (long)z * NS * NS;

    const int bm = blockIdx.y * 128, bn = blockIdx.x * 128;
    const int tid = threadIdx.x, warp = tid >> 5, lane = tid & 31;
    const int wm = (warp >> 1) * 32, wn = (warp & 1) * 64;
    const int g = lane >> 2, qd = lane & 3;

    if (EPI == 3 && tid < 64) dtab[tid] = dtab_g[tid];

    float acc[2][8][4];
#pragma unroll
    for (int i = 0; i < 2; i++)
#pragma unroll
        for (int j = 0; j < 8; j++)
#pragma unroll
            for (int t = 0; t < 4; t++) acc[i][j][t] = 0.f;

    const int nit = K / 64;
    const uint32_t smb = s2u(smraw);

    // ldmatrix per-thread offsets (bytes within stage)
    const uint32_t aoff = (uint32_t)((wm + (lane & 15)) * 144 + (lane >> 4) * 16);
    const uint32_t boff = (uint32_t)(18432 +
        (wn + (lane & 7) + ((lane >> 4) & 1) * 8) * 144 + ((lane >> 3) & 1) * 16);

    auto load_stage = [&](int s, int k0) {
        uint32_t abase = smb + s * STAGE_B;
        uint32_t bbase = abase + 18432;
#pragma unroll
        for (int j = 0; j < 4; j++) {
            int c = tid + j * 256;
            int row = c >> 3, ch = c & 7;
            cpa16(abase + row * 144 + ch * 16,
                  A + (long)(bm + row) * lda + k0 + ch * 8);
        }
#pragma unroll
        for (int j = 0; j < 4; j++) {
            int c = tid + j * 256;
            int row = c >> 3, ch = c & 7;
            cpa16(bbase + row * 144 + ch * 16,
                  B + (long)(bn + row) * ldb + k0 + ch * 8);
        }
    };

    load_stage(0, 0);  cp_commit();
    load_stage(1, 64); cp_commit();

    for (int it = 0; it < nit; ++it) {
        asm volatile("cp.async.wait_group 1;" ::: "memory");
        __syncthreads();
        if (it + 2 < nit) load_stage((it + 2) % 3, (it + 2) * 64);
        cp_commit();

        const uint32_t sbase = smb + (it % 3) * STAGE_B;
#pragma unroll
        for (int s = 0; s < 4; s++) {
            uint32_t af[2][4], bf[4][4];
#pragma unroll
            for (int mt = 0; mt < 2; mt++)
                LDSM4(af[mt][0], af[mt][1], af[mt][2], af[mt][3],
                      sbase + aoff + mt * 2304 + s * 32);
#pragma unroll
            for (int np = 0; np < 4; np++)
                LDSM4(bf[np][0], bf[np][1], bf[np][2], bf[np][3],
                      sbase + boff + np * 2304 + s * 32);
#pragma unroll
            for (int mt = 0; mt < 2; mt++)
#pragma unroll
                for (int nt = 0; nt < 8; nt++)
                    mma_f16(acc[mt][nt], af[mt],
                            bf[nt >> 1][(nt & 1) * 2], bf[nt >> 1][(nt & 1) * 2 + 1]);
        }
    }

    // ---------------- epilogue ----------------
    if (EPI == 3) {
        float rsacc[2][2];
#pragma unroll
        for (int mt = 0; mt < 2; mt++) { rsacc[mt][0] = 0.f; rsacc[mt][1] = 0.f; }
#pragma unroll
        for (int mt = 0; mt < 2; mt++) {
            int rl = bm + wm + mt * 16 + g;
#pragma unroll
            for (int nt = 0; nt < 8; nt++) {
                int c0 = bn + wn + nt * 8 + 2 * qd;
                long doff0 = ((long)z * NS + rl) * NS + c0;
                int2 dA = *(const int2*)(dep + doff0);
                float e0 = dA.x ? __expf(acc[mt][nt][0] * dtab[dA.x]) : 0.f;
                float e1 = dA.y ? __expf(acc[mt][nt][1] * dtab[dA.y]) : 0.f;
                *(float2*)(Cf + (long)rl * ldc + c0) = make_float2(e0, e1);
                __half2 h0 = __floats2half2_rn(e0, e1);
                *(__half2*)(Eh + (long)rl * NS + c0) = h0;
                rsacc[mt][0] += e0 + e1;
                long doff1 = ((long)z * NS + rl + 8) * NS + c0;
                int2 dB = *(const int2*)(dep + doff1);
                float e2 = dB.x ? __expf(acc[mt][nt][2] * dtab[dB.x]) : 0.f;
                float e3 = dB.y ? __expf(acc[mt][nt][3] * dtab[dB.y]) : 0.f;
                *(float2*)(Cf + (long)(rl + 8) * ldc + c0) = make_float2(e2, e3);
                __half2 h1 = __floats2half2_rn(e2, e3);
                *(__half2*)(Eh + (long)(rl + 8) * NS + c0) = h1;
                rsacc[mt][1] += e2 + e3;
            }
        }
#pragma unroll
        for (int mt = 0; mt < 2; mt++) {
            rsacc[mt][0] += __shfl_xor_sync(0xffffffff, rsacc[mt][0], 1);
            rsacc[mt][0] += __shfl_xor_sync(0xffffffff, rsacc[mt][0], 2);
            rsacc[mt][1] += __shfl_xor_sync(0xffffffff, rsacc[mt][1], 1);
            rsacc[mt][1] += __shfl_xor_sync(0xffffffff, rsacc[mt][1], 2);
        }
        if (qd == 0) {
#pragma unroll
            for (int mt = 0; mt < 2; mt++) {
                rs2[(warp & 1) * 128 + wm + mt * 16 + g] = rsacc[mt][0];
                rs2[(warp & 1) * 128 + wm + mt * 16 + g + 8] = rsacc[mt][1];
            }
        }
        __syncthreads();
        if (tid < 128)
            rsp[(long)blockIdx.x * BSROWS + (long)z * NS + bm + tid] =
                rs2[tid] + rs2[128 + tid];
    } else {
#pragma unroll
        for (int mt = 0; mt < 2; mt++) {
            int rl = bm + wm + mt * 16 + g;
            float r0inv = 1.f, r1inv = 1.f;
            if (EPI == 4) {
                r0inv = __frcp_rn(rsum[(long)z * NS + rl]);
                r1inv = __frcp_rn(rsum[(long)z * NS + rl + 8]);
            }
#pragma unroll
            for (int nt = 0; nt < 8; nt++) {
                int c0 = bn + wn + nt * 8 + 2 * qd;
                float v0 = acc[mt][nt][0], v1 = acc[mt][nt][1];
                float v2 = acc[mt][nt][2], v3 = acc[mt][nt][3];
                if (EPI == 1 || EPI == 2) {
                    float b0 = bias[c0], b1 = bias[c0 + 1];
                    v0 += b0; v1 += b1; v2 += b0; v3 += b1;
                }
                if (EPI == 2) { v0 = tanhf(v0); v1 = tanhf(v1); v2 = tanhf(v2); v3 = tanhf(v3); }
                if (EPI == 4) { v0 *= r0inv; v1 *= r0inv; v2 *= r1inv; v3 *= r1inv; }
                if (OUTH) {
                    __half2 h0 = __floats2half2_rn(v0, v1);
                    __half2 h1 = __floats2half2_rn(v2, v3);
                    *(__half2*)(Ch + (long)rl * ldc + c0) = h0;
                    *(__half2*)(Ch + (long)(rl + 8) * ldc + c0) = h1;
                } else {
                    *(float2*)(Cf + (long)rl * ldc + c0) = make_float2(v0, v1);
                    *(float2*)(Cf + (long)(rl + 8) * ldc + c0) = make_float2(v2, v3);
                }
            }
        }
    }
}

// ---------------------------------------------------------------------------
// launch
// ---------------------------------------------------------------------------
extern "C" void kernel_launch(void* const* d_in, const int* in_sizes, int n_in,
                              void* d_out, int out_size) {
    const int* inputs      = (const int*)d_in[0];
    const int* dependency  = (const int*)d_in[1];
    const float* embed     = (const float*)d_in[2];
    const float* dep_table = (const float*)d_in[3];
    const float* Wq = (const float*)d_in[4];
    const float* bq = (const float*)d_in[5];
    const float* Wk = (const float*)d_in[6];
    const float* bk = (const float*)d_in[7];
    const float* Wv = (const float*)d_in[8];
    const float* bv = (const float*)d_in[9];
    const float* W1 = (const float*)d_in[10];
    const float* b1 = (const float*)d_in[11];
    const float* W2 = (const float*)d_in[12];
    const float* b2 = (const float*)d_in[13];

    float* out = (float*)d_out;
    float* out_wm = out;          // [B,S,D]
    float* out_w  = out + XSZ;    // [B,S,S]

    __half *Xh, *QKVh, *Vth, *Eh, *WMh, *Hh, *Wth;
    float *B3, *RSP, *RSUM;
    cudaGetSymbolAddress((void**)&Xh, g_Xh);
    cudaGetSymbolAddress((void**)&QKVh, g_QKVh);
    cudaGetSymbolAddress((void**)&Vth, g_Vth);
    cudaGetSymbolAddress((void**)&Eh, g_Eh);
    cudaGetSymbolAddress((void**)&WMh, g_WMh);
    cudaGetSymbolAddress((void**)&Hh, g_Hh);
    cudaGetSymbolAddress((void**)&Wth, g_Wth);
    cudaGetSymbolAddress((void**)&B3, g_bias3);
    cudaGetSymbolAddress((void**)&RSP, g_rsp);
    cudaGetSymbolAddress((void**)&RSUM, g_rsum);

    __half* Qh = QKVh;
    __half* Kh = QKVh + XSZ;
    __half* Vh = QKVh + 2 * XSZ;

    cudaFuncSetAttribute(gemm_h<1, true>,  cudaFuncAttributeMaxDynamicSharedMemorySize, SMEM_DYN);
    cudaFuncSetAttribute(gemm_h<3, false>, cudaFuncAttributeMaxDynamicSharedMemorySize, SMEM_DYN);
    cudaFuncSetAttribute(gemm_h<4, true>,  cudaFuncAttributeMaxDynamicSharedMemorySize, SMEM_DYN);
    cudaFuncSetAttribute(gemm_h<2, true>,  cudaFuncAttributeMaxDynamicSharedMemorySize, SMEM_DYN);
    cudaFuncSetAttribute(gemm_h<1, false>, cudaFuncAttributeMaxDynamicSharedMemorySize, SMEM_DYN);

    // prep
    preroundTh<<<dim3(16, 16, 5), dim3(32, 8)>>>(Wq, Wk, Wv, W1, W2, Wth);
    copy_bias3<<<1, 512>>>(bq, bk, bv, B3);
    gather_h<<<16384, 128>>>(inputs, embed, Xh);

    // QKV fused (fp16 out)
    gemm_h<1, true><<<dim3(4, 128, 3), 256, SMEM_DYN>>>(
        Xh, Wth, B3, QKVh, nullptr, nullptr, nullptr, nullptr, nullptr,
        512, 512, 512, 512, 0, WELEMS, XSZ, 512);

    // V transpose (fp16)
    transVh<<<dim3(16, 32, 16), dim3(32, 8)>>>(Vh, Vth);

    // scores: S = Q K^T; exp/mask; fp32 -> out_w, fp16 -> Eh; partial rowsums
    gemm_h<3, false><<<dim3(8, 8, 16), 256, SMEM_DYN>>>(
        Qh, Kh, nullptr, out_w, Eh, dependency, dep_table, RSP, nullptr,
        512, 512, 512, 1024, (long)NS * ND, (long)NS * ND, (long)NS * NS, 0);

    rowsum_total<<<64, 256>>>(RSP, RSUM);

    // AV on unnormalized Eh; epilogue scales rows by 1/rowsum; fp16 out
    gemm_h<4, true><<<dim3(4, 8, 16), 256, SMEM_DYN>>>(
        Eh, Vth, nullptr, WMh, nullptr, nullptr, nullptr, nullptr, RSUM,
        1024, 1024, 1024, 512, (long)NS * NS, (long)NS * ND, (long)NS * ND, 0);

    // normalize weights output in place (fp32)
    normalize_kernel<<<(int)(WSZ / 1024), 256>>>(out_w, RSUM);

    // FFN
    dim3 gproj(4, 128, 1);
    gemm_h<2, true><<<gproj, 256, SMEM_DYN>>>(
        WMh, Wth + 3L * WELEMS, b1, Hh, nullptr, nullptr, nullptr, nullptr, nullptr,
        512, 512, 512, 512, 0, 0, 0, 0);
    gemm_h<1, false><<<gproj, 256, SMEM_DYN>>>(
        Hh, Wth + 4L * WELEMS, b2, out_wm, nullptr, nullptr, nullptr, nullptr, nullptr,
        512, 512, 512, 512, 0, 0, 0, 0);
}